// round 14
// baseline (speedup 1.0000x reference)
#include <cuda_runtime.h>

// ---------------------------------------------------------------------------
// Problem constants
// ---------------------------------------------------------------------------
constexpr int Nu = 50000, Np = 20000, IN = 256, EF = 64, H = 128;
constexpr int Ep = 200000, Ec = 800000, Eu = 300000;
constexpr int HH = H * H;
constexpr int SCAN_G = 64;

// ---------------------------------------------------------------------------
// Scratch (device global; allocation-free contract)
// ---------------------------------------------------------------------------
struct alignas(16) Scratch {
    float h_user[(size_t)Nu * H];
    float init_user[(size_t)Nu * H];
    float ctx[(size_t)Nu * H];
    float user_new[(size_t)Nu * H];
    float agg_ucu[(size_t)Nu * H];
    float h_post[(size_t)Np * H];
    float init_post[(size_t)Np * H];
    float post_enc[(size_t)Np * H];
    float post_new[(size_t)Np * H];
    float agg_pub[(size_t)Np * H];
    float agg_com[(size_t)Np * H];
    int cnt_pub_u[Nu]; int cnt_com_u[Nu]; int cnt_ucu_u[Nu]; int cnt_ucu_v[Nu];
    int cnt_pub_v[Np]; int cnt_com_v[Np];
    float inv_pub_u[Nu]; float inv_com_u[Nu]; float inv_ucu_v[Nu];
    float inv_pub_v[Np]; float inv_com_v[Np];
    int deg_user[Nu]; int deg_post[Np];
    float avgpost[IN];
    float cvec[H];
    float gm_user[H]; float gm_post[H];   // contiguous: single memset
    int nz[4];                            // padded so next member is 16B-aligned
    // CSR structures (built once per launch)
    int off_pub_v[Np + 1]; int off_com_v[Np + 1]; int off_ucu_v[Nu + 1];
    int off_com_u[Nu + 1]; int off_pub_u[Nu + 1];
    int cur_pub_v[Np]; int cur_com_v[Np]; int cur_ucu_v[Nu];
    int cur_com_u[Nu]; int cur_pub_u[Nu];
    int blocksums[5 * SCAN_G];
    int csr_pub_v[Ep]; int csr_com_v[Ec]; int csr_ucu_v[Eu];
    int csr_com_u[Ec]; int csr_pub_u[Ep];
    // tf32-converted, n-major (Wt[n][k]) weights. 16B alignment REQUIRED for
    // the uint4 loads in the mma kernels (R3 misaligned-address crash).
    alignas(16) unsigned Wt_up[128 * 256];
    alignas(16) unsigned Wt_pp[128 * 256];
    alignas(16) unsigned Wt_uce[128 * 256];
    alignas(16) unsigned Wt_cls[128 * 128];
    alignas(16) unsigned Wt_conv[128 * 64];
    alignas(16) unsigned Wt_ss[2][HH];   // Wself(l,0)+Wself(l,1)
    alignas(16) unsigned Wt_n0[2][HH];
    alignas(16) unsigned Wt_n1[2][HH];
    alignas(16) unsigned Wt_s2[2][HH];
    alignas(16) unsigned Wt_n2[2][HH];
    float b_post[2][H]; float b_user[2][H];
};
__device__ Scratch gS;

// ---------------------------------------------------------------------------
// Helpers
// ---------------------------------------------------------------------------
__device__ __forceinline__ float warp_sum(float v) {
#pragma unroll
    for (int o = 16; o; o >>= 1) v += __shfl_xor_sync(0xffffffffu, v, o);
    return v;
}

__device__ __forceinline__ void red2(float* p, float a, float b) {
    asm volatile("red.global.add.v2.f32 [%0], {%1,%2};"
                 :: "l"(p), "f"(a), "f"(b) : "memory");
}

__device__ __forceinline__ float lrelu(float x) { return x >= 0.f ? x : 0.01f * x; }

__device__ __forceinline__ unsigned f2tf(float x) {
    unsigned r;
    asm("cvt.rna.tf32.f32 %0, %1;" : "=r"(r) : "f"(x));
    return r;
}

__device__ __forceinline__ void mma_tf32(float c[4], const unsigned a[4], const unsigned b[2]) {
    asm volatile(
        "mma.sync.aligned.m16n8k8.row.col.f32.tf32.tf32.f32 "
        "{%0,%1,%2,%3},{%4,%5,%6,%7},{%8,%9},{%0,%1,%2,%3};"
        : "+f"(c[0]), "+f"(c[1]), "+f"(c[2]), "+f"(c[3])
        : "r"(a[0]), "r"(a[1]), "r"(a[2]), "r"(a[3]), "r"(b[0]), "r"(b[1]));
}

// Gather-sum a 512B feature row range via CSR (dual accumulator for MLP=2).
__device__ __forceinline__ float4 gath(const int* __restrict__ csr, int beg, int end,
                                       const float* __restrict__ feat, int lane) {
    float4 a = make_float4(0.f, 0.f, 0.f, 0.f);
    float4 b = make_float4(0.f, 0.f, 0.f, 0.f);
    int i = beg;
    for (; i + 1 < end; i += 2) {
        int s0 = csr[i], s1 = csr[i + 1];
        float4 v0 = ((const float4*)feat)[(size_t)s0 * 32 + lane];
        float4 v1 = ((const float4*)feat)[(size_t)s1 * 32 + lane];
        a.x += v0.x; a.y += v0.y; a.z += v0.z; a.w += v0.w;
        b.x += v1.x; b.y += v1.y; b.z += v1.z; b.w += v1.w;
    }
    if (i < end) {
        int s0 = csr[i];
        float4 v0 = ((const float4*)feat)[(size_t)s0 * 32 + lane];
        a.x += v0.x; a.y += v0.y; a.z += v0.z; a.w += v0.w;
    }
    a.x += b.x; a.y += b.y; a.z += b.z; a.w += b.w;
    return a;
}

// ---------------------------------------------------------------------------
// tf32 tensor-core GEMM, up to 3 independent JOBS per launch (block ranges),
// each job with up to 3 fused K-segments:
//   C[M,128] = act( sum_s (rs_s ⊙ A_s[M,Ks]) @ W_s[Ks,128] + bias )
// Optional fused epilogues:
//   gm  != nullptr: deg-masked column sums of the stored values -> gm[128]
//   out4!= nullptr: out4[M,4] = (activated tile) @ W2[128,4] + b2 (classifier)
// ---------------------------------------------------------------------------
struct Seg { const float* A; const unsigned* Wt; const float* rs; int K; };
struct GemmJob {
    Seg s0, s1, s2; int nseg;
    const float* bias; float* C; float* C2; int M; int act;
    const int* deg; float* gm;                       // fused colsum
    const float* W2; const float* b2; float* out4;   // fused classifier head
};

__global__ __launch_bounds__(256, 2) void gemm_multi(
    GemmJob j0, GemmJob j1, GemmJob j2, int start1, int start2)
{
    __shared__ __align__(16) unsigned As[128][20];
    __shared__ __align__(16) unsigned Bs[128][20];
    __shared__ float scol[128];
    __shared__ float sout[128][4];
    const int tid = threadIdx.x;
    const int lane = tid & 31, warp = tid >> 5;
    const int gid = lane >> 2, q = lane & 3;
    const int wm = warp & 3, wn = warp >> 2;

    GemmJob J;
    int lb = blockIdx.x;
    if (lb >= start2)      { J = j2; lb -= start2; }
    else if (lb >= start1) { J = j1; lb -= start1; }
    else                   { J = j0; }
    const int M = J.M;
    const int rowBase = lb * 128;
    const int lrow = tid >> 2;            // 0..63
    const int lk4 = (tid & 3) * 4;        // 0,4,8,12

    if (tid < 128) {
        scol[tid] = 0.f;
        sout[tid][0] = 0.f; sout[tid][1] = 0.f; sout[tid][2] = 0.f; sout[tid][3] = 0.f;
    }

    float acc[2][8][4];
#pragma unroll
    for (int mt = 0; mt < 2; mt++)
#pragma unroll
        for (int nt = 0; nt < 8; nt++)
#pragma unroll
            for (int i = 0; i < 4; i++) acc[mt][nt][i] = 0.f;

    Seg segs[3] = {J.s0, J.s1, J.s2};
    for (int s = 0; s < J.nseg; s++) {
        const float* A = segs[s].A;
        const unsigned* Wt = segs[s].Wt;
        const float* rs = segs[s].rs;
        const int K = segs[s].K;
        int r0 = rowBase + lrow;      if (r0 > M - 1) r0 = M - 1;
        int r1 = rowBase + lrow + 64; if (r1 > M - 1) r1 = M - 1;
        const float sc0 = rs ? rs[r0] : 1.f;
        const float sc1 = rs ? rs[r1] : 1.f;

        for (int k0 = 0; k0 < K; k0 += 16) {
            float4 av0 = *(const float4*)&A[(size_t)r0 * K + k0 + lk4];
            float4 av1 = *(const float4*)&A[(size_t)r1 * K + k0 + lk4];
            uint4 u0 = make_uint4(f2tf(av0.x * sc0), f2tf(av0.y * sc0),
                                  f2tf(av0.z * sc0), f2tf(av0.w * sc0));
            uint4 u1 = make_uint4(f2tf(av1.x * sc1), f2tf(av1.y * sc1),
                                  f2tf(av1.z * sc1), f2tf(av1.w * sc1));
            *(uint4*)&As[lrow][lk4] = u0;
            *(uint4*)&As[lrow + 64][lk4] = u1;
            *(uint4*)&Bs[lrow][lk4]      = *(const uint4*)&Wt[(size_t)lrow * K + k0 + lk4];
            *(uint4*)&Bs[lrow + 64][lk4] = *(const uint4*)&Wt[(size_t)(lrow + 64) * K + k0 + lk4];
            __syncthreads();

#pragma unroll
            for (int kk = 0; kk < 16; kk += 8) {
                unsigned a[2][4], b[8][2];
#pragma unroll
                for (int mt = 0; mt < 2; mt++) {
                    int r = wm * 32 + mt * 16 + gid;
                    a[mt][0] = As[r][kk + q];
                    a[mt][1] = As[r + 8][kk + q];
                    a[mt][2] = As[r][kk + q + 4];
                    a[mt][3] = As[r + 8][kk + q + 4];
                }
#pragma unroll
                for (int nt = 0; nt < 8; nt++) {
                    int n = wn * 64 + nt * 8 + gid;
                    b[nt][0] = Bs[n][kk + q];
                    b[nt][1] = Bs[n][kk + q + 4];
                }
#pragma unroll
                for (int mt = 0; mt < 2; mt++)
#pragma unroll
                    for (int nt = 0; nt < 8; nt++)
                        mma_tf32(acc[mt][nt], a[mt], b[nt]);
            }
            __syncthreads();
        }
    }

    // Epilogue: bias + activation (+ store / colsum / classifier head)
    const int act = J.act;
#pragma unroll
    for (int mt = 0; mt < 2; mt++) {
        int row0 = rowBase + wm * 32 + mt * 16 + gid;
        int row1 = row0 + 8;
        bool ok0 = row0 < M, ok1 = row1 < M;
        bool d0 = J.gm && ok0 && (J.deg[row0] > 0);
        bool d1 = J.gm && ok1 && (J.deg[row1] > 0);
        float o0[4] = {0.f, 0.f, 0.f, 0.f};
        float o1[4] = {0.f, 0.f, 0.f, 0.f};
#pragma unroll
        for (int nt = 0; nt < 8; nt++) {
            int col = wn * 64 + nt * 8 + q * 2;
            float b0 = J.bias[col], b1 = J.bias[col + 1];
            float v0 = acc[mt][nt][0] + b0, v1 = acc[mt][nt][1] + b1;
            float v2 = acc[mt][nt][2] + b0, v3 = acc[mt][nt][3] + b1;
            if (act == 1) { v0 = lrelu(v0); v1 = lrelu(v1); v2 = lrelu(v2); v3 = lrelu(v3); }
            else if (act == 2) {
                v0 = fmaxf(v0, 0.f); v1 = fmaxf(v1, 0.f);
                v2 = fmaxf(v2, 0.f); v3 = fmaxf(v3, 0.f);
            }
            if (J.C) {
                if (ok0) {
                    *(float2*)&J.C[(size_t)row0 * 128 + col] = make_float2(v0, v1);
                    if (J.C2) *(float2*)&J.C2[(size_t)row0 * 128 + col] = make_float2(v0, v1);
                }
                if (ok1) {
                    *(float2*)&J.C[(size_t)row1 * 128 + col] = make_float2(v2, v3);
                    if (J.C2) *(float2*)&J.C2[(size_t)row1 * 128 + col] = make_float2(v2, v3);
                }
            }
            if (J.gm) {
                float s0 = (d0 ? v0 : 0.f) + (d1 ? v2 : 0.f);
                float s1 = (d0 ? v1 : 0.f) + (d1 ? v3 : 0.f);
                if (s0 != 0.f) atomicAdd(&scol[col], s0);
                if (s1 != 0.f) atomicAdd(&scol[col + 1], s1);
            }
            if (J.out4) {
                float4 w0 = ((const float4*)J.W2)[col];
                float4 w1 = ((const float4*)J.W2)[col + 1];
                o0[0] += v0 * w0.x + v1 * w1.x; o0[1] += v0 * w0.y + v1 * w1.y;
                o0[2] += v0 * w0.z + v1 * w1.z; o0[3] += v0 * w0.w + v1 * w1.w;
                o1[0] += v2 * w0.x + v3 * w1.x; o1[1] += v2 * w0.y + v3 * w1.y;
                o1[2] += v2 * w0.z + v3 * w1.z; o1[3] += v2 * w0.w + v3 * w1.w;
            }
        }
        if (J.out4) {
#pragma unroll
            for (int c = 0; c < 4; c++) {
#pragma unroll
                for (int o = 1; o <= 2; o <<= 1) {
                    o0[c] += __shfl_xor_sync(0xffffffffu, o0[c], o);
                    o1[c] += __shfl_xor_sync(0xffffffffu, o1[c], o);
                }
            }
            if (q == 0) {
                int rl = wm * 32 + mt * 16 + gid;
#pragma unroll
                for (int c = 0; c < 4; c++) {
                    atomicAdd(&sout[rl][c], o0[c]);
                    atomicAdd(&sout[rl + 8][c], o1[c]);
                }
            }
        }
    }
    if (J.gm || J.out4) {
        __syncthreads();
        if (J.gm && tid < 128 && scol[tid] != 0.f) atomicAdd(&J.gm[tid], scol[tid]);
        if (J.out4) {
            // 512 outputs (128 rows x 4); 256 threads write 2 each
            for (int i = tid; i < 512; i += 256) {
                int rl = i >> 2, c = i & 3;
                int row = rowBase + rl;
                if (row < M) J.out4[(size_t)row * 4 + c] = sout[rl][c] + J.b2[c];
            }
        }
    }
}

// ---------------------------------------------------------------------------
// conv via tensor cores: per-edge cc = relu(LN(parent_feat@convW + cvec)),
// then ctx[ucu_u[e]] += cc. BM=128 edges, N=128, K=64.
// ---------------------------------------------------------------------------
__global__ __launch_bounds__(256, 2) void conv_mma_kernel(
    const float* __restrict__ A, const unsigned* __restrict__ Wt,
    const float* __restrict__ cvec, const float* __restrict__ gw,
    const float* __restrict__ be, const int* __restrict__ uidx,
    float* __restrict__ ctx, int M)
{
    __shared__ __align__(16) unsigned As[128][20];
    __shared__ __align__(16) unsigned Bs[128][20];
    __shared__ float rsum[128], rssq[128];
    const int tid = threadIdx.x;
    const int lane = tid & 31, warp = tid >> 5;
    const int gid = lane >> 2, q = lane & 3;
    const int wm = warp & 3, wn = warp >> 2;
    const int rowBase = blockIdx.x * 128;
    const int lrow = tid >> 2;
    const int lk4 = (tid & 3) * 4;

    float acc[2][8][4];
#pragma unroll
    for (int mt = 0; mt < 2; mt++)
#pragma unroll
        for (int nt = 0; nt < 8; nt++)
#pragma unroll
            for (int i = 0; i < 4; i++) acc[mt][nt][i] = 0.f;

    int r0 = rowBase + lrow;      if (r0 > M - 1) r0 = M - 1;
    int r1 = rowBase + lrow + 64; if (r1 > M - 1) r1 = M - 1;

    if (tid < 128) { rsum[tid] = 0.f; rssq[tid] = 0.f; }

    for (int k0 = 0; k0 < 64; k0 += 16) {
        float4 av0 = *(const float4*)&A[(size_t)r0 * 64 + k0 + lk4];
        float4 av1 = *(const float4*)&A[(size_t)r1 * 64 + k0 + lk4];
        *(uint4*)&As[lrow][lk4] = make_uint4(f2tf(av0.x), f2tf(av0.y), f2tf(av0.z), f2tf(av0.w));
        *(uint4*)&As[lrow + 64][lk4] = make_uint4(f2tf(av1.x), f2tf(av1.y), f2tf(av1.z), f2tf(av1.w));
        *(uint4*)&Bs[lrow][lk4]      = *(const uint4*)&Wt[(size_t)lrow * 64 + k0 + lk4];
        *(uint4*)&Bs[lrow + 64][lk4] = *(const uint4*)&Wt[(size_t)(lrow + 64) * 64 + k0 + lk4];
        __syncthreads();
#pragma unroll
        for (int kk = 0; kk < 16; kk += 8) {
            unsigned a[2][4], b[8][2];
#pragma unroll
            for (int mt = 0; mt < 2; mt++) {
                int r = wm * 32 + mt * 16 + gid;
                a[mt][0] = As[r][kk + q];
                a[mt][1] = As[r + 8][kk + q];
                a[mt][2] = As[r][kk + q + 4];
                a[mt][3] = As[r + 8][kk + q + 4];
            }
#pragma unroll
            for (int nt = 0; nt < 8; nt++) {
                int n = wn * 64 + nt * 8 + gid;
                b[nt][0] = Bs[n][kk + q];
                b[nt][1] = Bs[n][kk + q + 4];
            }
#pragma unroll
            for (int mt = 0; mt < 2; mt++)
#pragma unroll
                for (int nt = 0; nt < 8; nt++)
                    mma_tf32(acc[mt][nt], a[mt], b[nt]);
        }
        __syncthreads();
    }

    // add cvec; per-row partial sums (row0 uses c0,c1; row1=row0+8 uses c2,c3)
#pragma unroll
    for (int mt = 0; mt < 2; mt++) {
        float ps0 = 0.f, pq0 = 0.f, ps1 = 0.f, pq1 = 0.f;
#pragma unroll
        for (int nt = 0; nt < 8; nt++) {
            int col = wn * 64 + nt * 8 + q * 2;
            float cv0 = cvec[col], cv1 = cvec[col + 1];
            acc[mt][nt][0] += cv0; acc[mt][nt][1] += cv1;
            acc[mt][nt][2] += cv0; acc[mt][nt][3] += cv1;
            ps0 += acc[mt][nt][0] + acc[mt][nt][1];
            pq0 += acc[mt][nt][0] * acc[mt][nt][0] + acc[mt][nt][1] * acc[mt][nt][1];
            ps1 += acc[mt][nt][2] + acc[mt][nt][3];
            pq1 += acc[mt][nt][2] * acc[mt][nt][2] + acc[mt][nt][3] * acc[mt][nt][3];
        }
#pragma unroll
        for (int o = 1; o <= 2; o <<= 1) {
            ps0 += __shfl_xor_sync(0xffffffffu, ps0, o);
            pq0 += __shfl_xor_sync(0xffffffffu, pq0, o);
            ps1 += __shfl_xor_sync(0xffffffffu, ps1, o);
            pq1 += __shfl_xor_sync(0xffffffffu, pq1, o);
        }
        if (q == 0) {
            int rl = wm * 32 + mt * 16 + gid;
            atomicAdd(&rsum[rl], ps0); atomicAdd(&rssq[rl], pq0);
            atomicAdd(&rsum[rl + 8], ps1); atomicAdd(&rssq[rl + 8], pq1);
        }
    }
    __syncthreads();

    // normalize + relu + scatter
#pragma unroll
    for (int mt = 0; mt < 2; mt++) {
        int rl = wm * 32 + mt * 16 + gid;
        int row0 = rowBase + rl, row1 = row0 + 8;
        float m0 = rsum[rl] * (1.f / 128.f);
        float v0 = rssq[rl] * (1.f / 128.f) - m0 * m0;
        float rr0 = rsqrtf(v0 + 1e-5f);
        float m1 = rsum[rl + 8] * (1.f / 128.f);
        float v1 = rssq[rl + 8] * (1.f / 128.f) - m1 * m1;
        float rr1 = rsqrtf(v1 + 1e-5f);
        int u0 = (row0 < M) ? uidx[row0] : -1;
        int u1 = (row1 < M) ? uidx[row1] : -1;
#pragma unroll
        for (int nt = 0; nt < 8; nt++) {
            int col = wn * 64 + nt * 8 + q * 2;
            float g0 = gw[col], g1 = gw[col + 1];
            float b0 = be[col], b1 = be[col + 1];
            if (u0 >= 0) {
                float x0 = fmaxf((acc[mt][nt][0] - m0) * rr0 * g0 + b0, 0.f);
                float x1 = fmaxf((acc[mt][nt][1] - m0) * rr0 * g1 + b1, 0.f);
                red2(&ctx[(size_t)u0 * 128 + col], x0, x1);
            }
            if (u1 >= 0) {
                float x2 = fmaxf((acc[mt][nt][2] - m1) * rr1 * g0 + b0, 0.f);
                float x3 = fmaxf((acc[mt][nt][3] - m1) * rr1 * g1 + b1, 0.f);
                red2(&ctx[(size_t)u1 * 128 + col], x2, x3);
            }
        }
    }
}

// ---------------------------------------------------------------------------
// Weight preprocessing: dst[n*K+k] = tf32(src[k*128+n] (+ src2[k*128+n]))
// ---------------------------------------------------------------------------
struct WJob { const float* src; const float* src2; unsigned* dst; int K; };
struct WJobs { WJob j[15]; };

__global__ void wprep_kernel(WJobs js) {
    WJob J = js.j[blockIdx.y];
    int idx = blockIdx.x * 256 + threadIdx.x;
    if (idx >= 128 * J.K) return;
    int n = idx / J.K, k = idx % J.K;
    float v = J.src[(size_t)k * 128 + n];
    if (J.src2) v += J.src2[(size_t)k * 128 + n];
    J.dst[idx] = f2tf(v);
}

__global__ void bcomb_kernel(const float* __restrict__ bself, const float* __restrict__ bneigh) {
    int c = threadIdx.x;  // 128
#pragma unroll
    for (int l = 0; l < 2; l++) {
        gS.b_post[l][c] = bself[(l * 3 + 0) * H + c] + bself[(l * 3 + 1) * H + c]
                        + bneigh[(l * 3 + 0) * H + c] + bneigh[(l * 3 + 1) * H + c];
        gS.b_user[l][c] = bself[(l * 3 + 2) * H + c] + bneigh[(l * 3 + 2) * H + c];
    }
}

// ---------------------------------------------------------------------------
// Counts / degrees
// ---------------------------------------------------------------------------
struct CJob { const int* idx; int n; int* cnt; };
__global__ void count6_kernel(CJob a, CJob b, CJob c, CJob d, CJob e, CJob f) {
    CJob js[6] = {a, b, c, d, e, f};
    CJob J = js[blockIdx.y];
    int i = blockIdx.x * 256 + threadIdx.x;
    if (i < J.n) atomicAdd(&J.cnt[J.idx[i]], 1);
}

// user (i < Nu) and post (i - Nu < Np) prep in one launch
__global__ void prep_all_kernel() {
    int i = blockIdx.x * blockDim.x + threadIdx.x;
    int flag = 0, which = -1;
    if (i < Nu) {
        int a = gS.cnt_pub_u[i], b = gS.cnt_com_u[i];
        int c = gS.cnt_ucu_u[i], d = gS.cnt_ucu_v[i];
        gS.inv_pub_u[i] = 1.f / (float)(a > 1 ? a : 1);
        gS.inv_com_u[i] = 1.f / (float)(b > 1 ? b : 1);
        gS.inv_ucu_v[i] = 1.f / (float)(d > 1 ? d : 1);
        int deg = a + b + c + d;
        gS.deg_user[i] = deg;
        flag = deg > 0; which = 0;
    } else {
        int p = i - Nu;
        if (p < Np) {
            int a = gS.cnt_pub_v[p], b = gS.cnt_com_v[p];
            gS.inv_pub_v[p] = 1.f / (float)(a > 1 ? a : 1);
            gS.inv_com_v[p] = 1.f / (float)(b > 1 ? b : 1);
            int deg = a + b;
            gS.deg_post[p] = deg;
            flag = deg > 0; which = 1;
        }
    }
    unsigned m0 = __ballot_sync(0xffffffffu, flag && which == 0);
    unsigned m1 = __ballot_sync(0xffffffffu, flag && which == 1);
    if ((threadIdx.x & 31) == 0) {
        if (m0) atomicAdd(&gS.nz[0], __popc(m0));
        if (m1) atomicAdd(&gS.nz[1], __popc(m1));
    }
}

// ---------------------------------------------------------------------------
// CSR build: exclusive scan of counts (3 kernels, 5 jobs batched) + binning
// ---------------------------------------------------------------------------
struct ScanJob { const int* cnt; int N; int* off; int* cur; };
struct ScanJobs { ScanJob j[5]; };

__global__ void scan1_kernel(ScanJobs js, int* __restrict__ bsum) {
    ScanJob J = js.j[blockIdx.y];
    int b = blockIdx.x, t = threadIdx.x;
    int C = (J.N + SCAN_G - 1) / SCAN_G;
    int tseg = (C + 255) / 256;
    int base = b * C + t * tseg;
    int endv = min(base + tseg, min((b + 1) * C, J.N));
    int tsum = 0;
    for (int i = base; i < endv; i++) tsum += J.cnt[i];
    __shared__ int s[256];
    s[t] = tsum; __syncthreads();
    for (int o = 1; o < 256; o <<= 1) {
        int v = (t >= o) ? s[t - o] : 0;
        __syncthreads(); s[t] += v; __syncthreads();
    }
    if (t == 255) bsum[blockIdx.y * SCAN_G + b] = s[255];
}

__global__ void scan2_kernel(int* __restrict__ bsum) {
    int j = blockIdx.x, t = threadIdx.x;  // 64 threads
    __shared__ int s[SCAN_G];
    int v = bsum[j * SCAN_G + t];
    s[t] = v; __syncthreads();
    for (int o = 1; o < SCAN_G; o <<= 1) {
        int x = (t >= o) ? s[t - o] : 0;
        __syncthreads(); s[t] += x; __syncthreads();
    }
    bsum[j * SCAN_G + t] = s[t] - v;  // exclusive
}

__global__ void scan3_kernel(ScanJobs js, const int* __restrict__ bsum) {
    ScanJob J = js.j[blockIdx.y];
    int b = blockIdx.x, t = threadIdx.x;
    int C = (J.N + SCAN_G - 1) / SCAN_G;
    int tseg = (C + 255) / 256;
    int base = b * C + t * tseg;
    int endv = min(base + tseg, min((b + 1) * C, J.N));
    int tsum = 0;
    for (int i = base; i < endv; i++) tsum += J.cnt[i];
    __shared__ int s[256];
    s[t] = tsum; __syncthreads();
    for (int o = 1; o < 256; o <<= 1) {
        int v = (t >= o) ? s[t - o] : 0;
        __syncthreads(); s[t] += v; __syncthreads();
    }
    int running = bsum[blockIdx.y * SCAN_G + b] + (s[t] - tsum);
    for (int i = base; i < endv; i++) {
        J.off[i] = running;
        J.cur[i] = running;
        running += J.cnt[i];
    }
    if (base < J.N && endv == J.N) J.off[J.N] = running;
}

struct BJob { const int* dst; const int* val; int n; int* cur; int* csr; };
__global__ void bin5_kernel(BJob a, BJob b, BJob c, BJob d, BJob e) {
    BJob js[5] = {a, b, c, d, e};
    BJob J = js[blockIdx.y];
    int i = blockIdx.x * 256 + threadIdx.x;
    if (i < J.n) {
        int p = atomicAdd(&J.cur[J.dst[i]], 1);
        J.csr[p] = J.val[i];
    }
}

// ---------------------------------------------------------------------------
// CSR gather kernels (replace the atomic scatters). One launch covers both
// post (w < Np) and user (w - Np < Nu) destinations.
// ---------------------------------------------------------------------------
__global__ void gather_all_kernel(const float* __restrict__ hu) {
    int w = (blockIdx.x * 256 + threadIdx.x) >> 5;
    int lane = threadIdx.x & 31;
    if (w < Np) {
        float4 p = gath(gS.csr_pub_v, gS.off_pub_v[w], gS.off_pub_v[w + 1], hu, lane);
        float4 c = gath(gS.csr_com_v, gS.off_com_v[w], gS.off_com_v[w + 1], hu, lane);
        ((float4*)gS.agg_pub)[(size_t)w * 32 + lane] = p;
        ((float4*)gS.agg_com)[(size_t)w * 32 + lane] = c;
    } else {
        int u = w - Np;
        if (u >= Nu) return;
        float4 a = gath(gS.csr_ucu_v, gS.off_ucu_v[u], gS.off_ucu_v[u + 1], hu, lane);
        ((float4*)gS.agg_ucu)[(size_t)u * 32 + lane] = a;
    }
}

// ctx gather (comment/publish post means) + conv ctx + blend into h_user
__global__ void ctx_blend_kernel() {
    int u = (blockIdx.x * 256 + threadIdx.x) >> 5;
    int lane = threadIdx.x & 31;
    if (u >= Nu) return;
    float4 g1 = gath(gS.csr_com_u, gS.off_com_u[u], gS.off_com_u[u + 1], gS.post_enc, lane);
    float4 g2 = gath(gS.csr_pub_u, gS.off_pub_u[u], gS.off_pub_u[u + 1], gS.post_enc, lane);
    float s1 = 0.3f * gS.inv_com_u[u];
    float s2 = 0.5f * gS.inv_pub_u[u];
    float4 cv = ((const float4*)gS.ctx)[(size_t)u * 32 + lane];
    cv.x += s1 * g1.x + s2 * g2.x;
    cv.y += s1 * g1.y + s2 * g2.y;
    cv.z += s1 * g1.z + s2 * g2.z;
    cv.w += s1 * g1.w + s2 * g2.w;
    float4 h = ((const float4*)gS.h_user)[(size_t)u * 32 + lane];
    h.x = 0.7f * h.x + 0.3f * cv.x;
    h.y = 0.7f * h.y + 0.3f * cv.y;
    h.z = 0.7f * h.z + 0.3f * cv.z;
    h.w = 0.7f * h.w + 0.3f * cv.w;
    ((float4*)gS.h_user)[(size_t)u * 32 + lane] = h;
}

// ---------------------------------------------------------------------------
// Misc small kernels
// ---------------------------------------------------------------------------
__global__ void avgpost_kernel(const float* __restrict__ post_x) {
    int col = threadIdx.x;                 // 256 threads = 256 cols
    float s = 0.f;
    for (int r = blockIdx.x; r < Np; r += gridDim.x)
        s += post_x[(size_t)r * IN + col];
    atomicAdd(&gS.avgpost[col], s);
}

__global__ void cvec_kernel(const float* __restrict__ conv_W, const float* __restrict__ conv_b) {
    int c = threadIdx.x;                   // 128 threads
    float s = conv_b[c];
    const float scale = 1.f / (float)Np;
    for (int k = 0; k < IN; k++)
        s += gS.avgpost[k] * scale * conv_W[(size_t)(EF + k) * H + c];
    gS.cvec[c] = s;
}

// fix_zero_degree + LayerNorm (+ optional leaky relu), user+post in ONE
// launch: flat warp index w in [0, Nu+Np).
template <bool LRELU>
__global__ void fixln_all_kernel(const float* __restrict__ lug, const float* __restrict__ lub,
                                 const float* __restrict__ lpg, const float* __restrict__ lpb) {
    int w = (blockIdx.x * blockDim.x + threadIdx.x) >> 5;
    int lane = threadIdx.x & 31;
    const float *hn, *init, *gm, *g, *b;
    const int* deg;
    float* out;
    int nzi;
    if (w < Nu) {
        hn = gS.user_new; init = gS.init_user; deg = gS.deg_user; gm = gS.gm_user;
        g = lug; b = lub; out = gS.h_user; nzi = 0;
    } else {
        w -= Nu;
        if (w >= Np) return;
        hn = gS.post_new; init = gS.init_post; deg = gS.deg_post; gm = gS.gm_post;
        g = lpg; b = lpb; out = gS.h_post; nzi = 1;
    }
    float4 v;
    if (deg[w] == 0) {
        float nz = fmaxf((float)gS.nz[nzi], 1.f);
        float4 e = ((const float4*)init)[(size_t)w * 32 + lane];
        float4 gv = ((const float4*)gm)[lane];
        v.x = 0.9f * e.x + 0.1f * gv.x / nz;
        v.y = 0.9f * e.y + 0.1f * gv.y / nz;
        v.z = 0.9f * e.z + 0.1f * gv.z / nz;
        v.w = 0.9f * e.w + 0.1f * gv.w / nz;
    } else {
        v = ((const float4*)hn)[(size_t)w * 32 + lane];
    }
    float s  = warp_sum(v.x + v.y + v.z + v.w);
    float ss = warp_sum(v.x * v.x + v.y * v.y + v.z * v.z + v.w * v.w);
    float mean = s * (1.f / 128.f);
    float var = ss * (1.f / 128.f) - mean * mean;
    float r = rsqrtf(var + 1e-5f);
    float4 gg = ((const float4*)g)[lane], bb = ((const float4*)b)[lane];
    v.x = (v.x - mean) * r * gg.x + bb.x;
    v.y = (v.y - mean) * r * gg.y + bb.y;
    v.z = (v.z - mean) * r * gg.z + bb.z;
    v.w = (v.w - mean) * r * gg.w + bb.w;
    if (LRELU) { v.x = lrelu(v.x); v.y = lrelu(v.y); v.z = lrelu(v.z); v.w = lrelu(v.w); }
    ((float4*)out)[(size_t)w * 32 + lane] = v;
}

// ---------------------------------------------------------------------------
// Host orchestration
// ---------------------------------------------------------------------------
extern "C" void kernel_launch(void* const* d_in, const int* in_sizes, int n_in,
                              void* d_out, int out_size) {
    const float* user_x      = (const float*)d_in[0];
    const float* post_x      = (const float*)d_in[1];
    const float* parent_feat = (const float*)d_in[2];
    const float* user_proj_W = (const float*)d_in[3];
    const float* user_proj_b = (const float*)d_in[4];
    const float* post_proj_W = (const float*)d_in[5];
    const float* post_proj_b = (const float*)d_in[6];
    const float* conv_W      = (const float*)d_in[7];
    const float* conv_b      = (const float*)d_in[8];
    const float* conv_g      = (const float*)d_in[9];
    const float* conv_beta   = (const float*)d_in[10];
    const float* uce_W       = (const float*)d_in[11];
    const float* uce_b       = (const float*)d_in[12];
    const float* Wself       = (const float*)d_in[13];
    const float* bself       = (const float*)d_in[14];
    const float* Wneigh      = (const float*)d_in[15];
    const float* bneigh      = (const float*)d_in[16];
    const float* ln_user_g   = (const float*)d_in[17];
    const float* ln_user_b   = (const float*)d_in[18];
    const float* ln_post_g   = (const float*)d_in[19];
    const float* ln_post_b   = (const float*)d_in[20];
    const float* cls_W1      = (const float*)d_in[21];
    const float* cls_b1      = (const float*)d_in[22];
    const float* cls_W2      = (const float*)d_in[23];
    const float* cls_b2      = (const float*)d_in[24];
    const int* publish_u     = (const int*)d_in[25];
    const int* publish_v     = (const int*)d_in[26];
    const int* comment_u     = (const int*)d_in[27];
    const int* comment_v     = (const int*)d_in[28];
    const int* ucu_u         = (const int*)d_in[29];
    const int* ucu_v         = (const int*)d_in[30];
    float* out = (float*)d_out;

    Scratch* S = nullptr;
    cudaGetSymbolAddress((void**)&S, gS);

    const int NBu = (Nu + 127) / 128;   // 391
    const int NBp = (Np + 127) / 128;   // 157

    // --- zero per-launch accumulators ---------------------------------------
    cudaMemsetAsync(S->cnt_pub_u, 0, sizeof(int) * (size_t)(4 * Nu + 2 * Np), 0);
    cudaMemsetAsync(S->nz, 0, sizeof(int) * 4, 0);
    cudaMemsetAsync(S->avgpost, 0, sizeof(float) * IN, 0);
    cudaMemsetAsync(S->ctx, 0, sizeof(float) * (size_t)Nu * H, 0);

    // --- counts / degrees ----------------------------------------------------
    {
        CJob c0 = {publish_u, Ep, S->cnt_pub_u};
        CJob c1 = {publish_v, Ep, S->cnt_pub_v};
        CJob c2 = {comment_u, Ec, S->cnt_com_u};
        CJob c3 = {comment_v, Ec, S->cnt_com_v};
        CJob c4 = {ucu_u, Eu, S->cnt_ucu_u};
        CJob c5 = {ucu_v, Eu, S->cnt_ucu_v};
        dim3 g((Ec + 255) / 256, 6);
        count6_kernel<<<g, 256>>>(c0, c1, c2, c3, c4, c5);
    }
    prep_all_kernel<<<(Nu + Np + 255) / 256, 256>>>();

    // --- CSR build (scan + bin) ----------------------------------------------
    {
        ScanJobs sj;
        sj.j[0] = {S->cnt_pub_v, Np, S->off_pub_v, S->cur_pub_v};
        sj.j[1] = {S->cnt_com_v, Np, S->off_com_v, S->cur_com_v};
        sj.j[2] = {S->cnt_ucu_v, Nu, S->off_ucu_v, S->cur_ucu_v};
        sj.j[3] = {S->cnt_com_u, Nu, S->off_com_u, S->cur_com_u};
        sj.j[4] = {S->cnt_pub_u, Nu, S->off_pub_u, S->cur_pub_u};
        dim3 g1(SCAN_G, 5);
        scan1_kernel<<<g1, 256>>>(sj, S->blocksums);
        scan2_kernel<<<5, SCAN_G>>>(S->blocksums);
        scan3_kernel<<<g1, 256>>>(sj, S->blocksums);

        BJob b0 = {publish_v, publish_u, Ep, S->cur_pub_v, S->csr_pub_v};
        BJob b1 = {comment_v, comment_u, Ec, S->cur_com_v, S->csr_com_v};
        BJob b2 = {ucu_v, ucu_u, Eu, S->cur_ucu_v, S->csr_ucu_v};
        BJob b3 = {comment_u, comment_v, Ec, S->cur_com_u, S->csr_com_u};
        BJob b4 = {publish_u, publish_v, Ep, S->cur_pub_u, S->csr_pub_u};
        dim3 gb((Ec + 255) / 256, 5);
        bin5_kernel<<<gb, 256>>>(b0, b1, b2, b3, b4);
    }

    // --- constants -----------------------------------------------------------
    avgpost_kernel<<<512, 256>>>(post_x);
    cvec_kernel<<<1, 128>>>(conv_W, conv_b);

    // --- weight preprocessing (transpose + tf32) -----------------------------
    {
        WJobs js;
        js.j[0] = {user_proj_W, nullptr, S->Wt_up, 256};
        js.j[1] = {post_proj_W, nullptr, S->Wt_pp, 256};
        js.j[2] = {uce_W, nullptr, S->Wt_uce, 256};
        js.j[3] = {cls_W1, nullptr, S->Wt_cls, 128};
        js.j[4] = {conv_W, nullptr, S->Wt_conv, 64};   // conv_W[:64] rows only
        for (int l = 0; l < 2; l++) {
            js.j[5 + 5 * l + 0] = {Wself + (size_t)(l * 3 + 0) * HH, Wself + (size_t)(l * 3 + 1) * HH, S->Wt_ss[l], 128};
            js.j[5 + 5 * l + 1] = {Wneigh + (size_t)(l * 3 + 0) * HH, nullptr, S->Wt_n0[l], 128};
            js.j[5 + 5 * l + 2] = {Wneigh + (size_t)(l * 3 + 1) * HH, nullptr, S->Wt_n1[l], 128};
            js.j[5 + 5 * l + 3] = {Wself + (size_t)(l * 3 + 2) * HH, nullptr, S->Wt_s2[l], 128};
            js.j[5 + 5 * l + 4] = {Wneigh + (size_t)(l * 3 + 2) * HH, nullptr, S->Wt_n2[l], 128};
        }
        dim3 g(128, 15);
        wprep_kernel<<<g, 256>>>(js);
    }
    bcomb_kernel<<<1, 128>>>(bself, bneigh);

    Seg z = {nullptr, nullptr, nullptr, 0};
    GemmJob jz = {z, z, z, 0, nullptr, nullptr, nullptr, 0, 0,
                  nullptr, nullptr, nullptr, nullptr, nullptr};

    // --- input projections: 3 GEMM jobs in ONE launch ------------------------
    {
        GemmJob a = {{user_x, S->Wt_up, nullptr, 256}, z, z, 1,
                     user_proj_b, S->h_user, S->init_user, Nu, 1,
                     nullptr, nullptr, nullptr, nullptr, nullptr};
        GemmJob b = {{post_x, S->Wt_pp, nullptr, 256}, z, z, 1,
                     post_proj_b, S->h_post, S->init_post, Np, 1,
                     nullptr, nullptr, nullptr, nullptr, nullptr};
        GemmJob c = {{post_x, S->Wt_uce, nullptr, 256}, z, z, 1,
                     uce_b, S->post_enc, nullptr, Np, 2,
                     nullptr, nullptr, nullptr, nullptr, nullptr};
        gemm_multi<<<NBu + 2 * NBp, 256>>>(a, b, c, NBu, NBu + NBp);
    }

    // --- ctx: tensor-core conv edge-GEMM scatter + CSR gathers + blend --------
    conv_mma_kernel<<<(Eu + 127) / 128, 256>>>(parent_feat, S->Wt_conv, S->cvec, conv_g, conv_beta, ucu_u, S->ctx, Eu);
    ctx_blend_kernel<<<((size_t)Nu * 32 + 255) / 256, 256>>>();

    // --- SAGE layers ----------------------------------------------------------
    for (int l = 0; l < 2; l++) {
        cudaMemsetAsync(S->gm_user, 0, sizeof(float) * 2 * H, 0);  // gm_user + gm_post
        gather_all_kernel<<<((size_t)(Np + Nu) * 32 + 255) / 256, 256>>>(S->h_user);

        // post_new and user_new in ONE launch (2 jobs), colsum fused in epilogue
        {
            GemmJob a = {{S->h_post, S->Wt_ss[l], nullptr, 128},
                         {S->agg_pub, S->Wt_n0[l], S->inv_pub_v, 128},
                         {S->agg_com, S->Wt_n1[l], S->inv_com_v, 128}, 3,
                         S->b_post[l], S->post_new, nullptr, Np, 0,
                         S->deg_post, S->gm_post, nullptr, nullptr, nullptr};
            GemmJob b = {{S->h_user, S->Wt_s2[l], nullptr, 128},
                         {S->agg_ucu, S->Wt_n2[l], S->inv_ucu_v, 128}, z, 2,
                         S->b_user[l], S->user_new, nullptr, Nu, 0,
                         S->deg_user, S->gm_user, nullptr, nullptr, nullptr};
            b.act = 0;
            gemm_multi<<<NBp + NBu, 256>>>(a, b, jz, NBp, NBp + NBu);
        }

        if (l == 0)
            fixln_all_kernel<true><<<((size_t)(Nu + Np) * 32 + 255) / 256, 256>>>(ln_user_g, ln_user_b, ln_post_g, ln_post_b);
        else
            fixln_all_kernel<false><<<((size_t)(Nu + Np) * 32 + 255) / 256, 256>>>(ln_user_g, ln_user_b, ln_post_g, ln_post_b);
    }

    // --- classifier: GEMM with fused 128x4 head (no cls2 launch) --------------
    {
        GemmJob a = {{S->h_user, S->Wt_cls, nullptr, 128}, z, z, 1,
                     cls_b1, nullptr, nullptr, Nu, 1,
                     nullptr, nullptr, cls_W2, cls_b2, out};
        gemm_multi<<<NBu, 256>>>(a, jz, jz, NBu, NBu);
    }
}